// round 11
// baseline (speedup 1.0000x reference)
#include <cuda_runtime.h>
#include <math.h>

// Problem constants (fixed by the dataset)
#define B_    256
#define S_    196
#define RNN_  1024
#define ATTH_ 512
#define NSPLIT 4
#define SCHUNK 49   // 196 / 4
#define KSPLIT 16   // k1 split-k factor
#define BPB    2    // batches per k23 block
#define NBY    (B_ / BPB)   // 128

// Scratch (allocation-free: __device__ globals; zero-initialized)
__device__ float g_att_h_part[KSPLIT * B_ * ATTH_];  // 8 MB (k1 partials)
__device__ float g_scores[B_ * S_];                  // 200 KB
__device__ float g_part[NSPLIT * B_ * RNN_];         // 4 MB (k3 partials)
__device__ int   g_rdy[B_];                          // per-batch score tickets
__device__ int   g_cnt[B_];                          // per-batch partial tickets

// ---------------------------------------------------------------------------
// HW tanh: MUFU.TANH (abs err ~5e-4; measured output rel err ~3e-6, gate 1e-3)
// ---------------------------------------------------------------------------
__device__ __forceinline__ float tanh_approx(float x)
{
    float y;
    asm("tanh.approx.f32 %0, %1;" : "=f"(y) : "f"(x));
    return y;
}

// ---------------------------------------------------------------------------
// K1: partial att_h: part[kz][b][a] = sum_{k in chunk kz} h[b,k] * W[a,k]
// 64x64 tile, BK=32, 8x4 microtile (32 FMA per 3 LDS.128 -> crossbar relief),
// 128 threads, double-buffered smem, split-k=16 -> 512 blocks (~14 warps/SM).
// ---------------------------------------------------------------------------
__global__ __launch_bounds__(128) void k1_h2att(
    const float* __restrict__ h, const float* __restrict__ w,
    float* __restrict__ part)
{
    __shared__ float sh[2][32][72];   // [buf][k][b(64)]
    __shared__ float sw[2][32][72];   // [buf][k][a(64)]

    const int t  = threadIdx.x;
    const int a0 = blockIdx.x * 64;
    const int b0 = blockIdx.y * 64;
    const int kz = blockIdx.z;
    const int tx = t & 15;            // a-dim (x4)
    const int ty = t >> 4;            // b-dim (x8), 0..7

    // global-load mapping: 4 float4 per array per thread per 32-k tile
    const int lr = t >> 3;            // 0..15
    const int lc = (t & 7) * 4;       // 0,4,..,28

    const size_t kbase = (size_t)kz * (RNN_ / KSPLIT);   // 64-k chunk
    const float* hp[4];
    const float* wp[4];
    #pragma unroll
    for (int g = 0; g < 4; g++) {
        hp[g] = &h[(size_t)(b0 + lr + g * 16) * RNN_ + kbase + lc];
        wp[g] = &w[(size_t)(a0 + lr + g * 16) * RNN_ + kbase + lc];
    }

    // preload tile 0
    float4 hv[4], wv4[4];
    #pragma unroll
    for (int g = 0; g < 4; g++) { hv[g] = *(const float4*)hp[g]; wv4[g] = *(const float4*)wp[g]; }
    #pragma unroll
    for (int g = 0; g < 4; g++)
        #pragma unroll
        for (int c = 0; c < 4; c++) {
            sh[0][lc + c][lr + g * 16] = (&hv[g].x)[c];
            sw[0][lc + c][lr + g * 16] = (&wv4[g].x)[c];
        }
    __syncthreads();

    float acc[8][4] = {};

    const int NT = RNN_ / KSPLIT / 32;   // 2 k-tiles
    #pragma unroll
    for (int kt = 0; kt < NT; kt++) {
        const int buf = kt & 1;
        if (kt + 1 < NT) {
            #pragma unroll
            for (int g = 0; g < 4; g++) {
                hv[g]  = *(const float4*)(hp[g] + (kt + 1) * 32);
                wv4[g] = *(const float4*)(wp[g] + (kt + 1) * 32);
            }
        }
        #pragma unroll
        for (int kk = 0; kk < 32; kk++) {
            float4 h0 = *(const float4*)&sh[buf][kk][ty * 8];
            float4 h1 = *(const float4*)&sh[buf][kk][ty * 8 + 4];
            float4 wv = *(const float4*)&sw[buf][kk][tx * 4];
            #pragma unroll
            for (int j = 0; j < 4; j++) {
                const float wj = (&wv.x)[j];
                acc[0][j] += h0.x * wj;
                acc[1][j] += h0.y * wj;
                acc[2][j] += h0.z * wj;
                acc[3][j] += h0.w * wj;
                acc[4][j] += h1.x * wj;
                acc[5][j] += h1.y * wj;
                acc[6][j] += h1.z * wj;
                acc[7][j] += h1.w * wj;
            }
        }
        __syncthreads();
        if (kt + 1 < NT) {
            const int nb = buf ^ 1;
            #pragma unroll
            for (int g = 0; g < 4; g++)
                #pragma unroll
                for (int c = 0; c < 4; c++) {
                    sh[nb][lc + c][lr + g * 16] = (&hv[g].x)[c];
                    sw[nb][lc + c][lr + g * 16] = (&wv4[g].x)[c];
                }
            __syncthreads();
        }
    }

    float* op = part + (size_t)kz * B_ * ATTH_;
    #pragma unroll
    for (int i = 0; i < 8; i++) {
        const int bb = b0 + ty * 8 + i;
        float4 r = make_float4(acc[i][0], acc[i][1], acc[i][2], acc[i][3]);
        *(float4*)&op[(size_t)bb * ATTH_ + a0 + tx * 4] = r;
    }
}

// ---------------------------------------------------------------------------
// helpers
// ---------------------------------------------------------------------------
__device__ __forceinline__ float row_score(
    const float4 v[4], const float4* __restrict__ ah4,
    const float4* __restrict__ wa4, int lane)
{
    float acc = 0.f;
    #pragma unroll
    for (int i = 0; i < 4; i++) {
        float4 a  = ah4[lane + i * 32];
        float4 wv = wa4[lane + i * 32];
        acc += tanh_approx(v[i].x + a.x) * wv.x + tanh_approx(v[i].y + a.y) * wv.y
             + tanh_approx(v[i].z + a.z) * wv.z + tanh_approx(v[i].w + a.w) * wv.w;
    }
    return acc;
}

__device__ __forceinline__ void load_row(
    float4 v[4], const float4* __restrict__ ps, int lane)
{
    v[0] = __ldcs(&ps[lane]);
    v[1] = __ldcs(&ps[lane + 32]);
    v[2] = __ldcs(&ps[lane + 64]);
    v[3] = __ldcs(&ps[lane + 96]);
}

// ---------------------------------------------------------------------------
// K23: fused scores + softmax + weighted sum; TWO batches per block so the
// second batch's phase-A fills the first batch's handoff bubble.
// grid = (NSPLIT, 128) = 512 blocks (all resident -> spins deadlock-free).
// ---------------------------------------------------------------------------
__global__ __launch_bounds__(128, 8) void k23_fused(
    const float* __restrict__ p, const float* __restrict__ att_h_part,
    const float* __restrict__ bias, const float* __restrict__ w_alpha,
    const float* __restrict__ att, float* __restrict__ scores,
    float* __restrict__ part, float* __restrict__ out)
{
    const int split = blockIdx.x;
    const int t     = threadIdx.x;
    const int warp  = t >> 5, lane = t & 31;
    const int s_lo  = split * SCHUNK;

    int bs[BPB];
    bs[0] = blockIdx.y;
    bs[1] = blockIdx.y + NBY;

    __shared__ float4 ah4[BPB][ATTH_ / 4];
    __shared__ float4 wa4[ATTH_ / 4];
    __shared__ float  es[S_];
    __shared__ float  red[128];
    __shared__ float  w_s[SCHUNK];
    __shared__ int    is_last;

    // --- assemble att_h for both batches from k1 partials + bias (L2-hot) ---
    {
        float4 bz = ((const float4*)bias)[t];
        wa4[t] = ((const float4*)w_alpha)[t];
        #pragma unroll
        for (int bi = 0; bi < BPB; bi++) {
            float4 r = bz;
            #pragma unroll
            for (int kz = 0; kz < KSPLIT; kz++) {
                const float4 v = ((const float4*)(att_h_part
                    + ((size_t)kz * B_ + bs[bi]) * ATTH_))[t];
                r.x += v.x; r.y += v.y; r.z += v.z; r.w += v.w;
            }
            ah4[bi][t] = r;
        }
    }
    __syncthreads();

    // --- Phase A for both batches (publish ticket after each) ---
    #pragma unroll
    for (int bi = 0; bi < BPB; bi++) {
        const int b = bs[bi];
        const float4* pb = (const float4*)(p + (size_t)b * S_ * ATTH_);
        int r = warp;                       // warp w: rows w, w+4, ...
        float4 cur[4];
        load_row(cur, pb + (size_t)(s_lo + r) * (ATTH_ / 4), lane);
        while (r < SCHUNK) {
            const int rn = r + 4;
            float4 nxt[4];
            if (rn < SCHUNK)
                load_row(nxt, pb + (size_t)(s_lo + rn) * (ATTH_ / 4), lane);
            float acc = row_score(cur, ah4[bi], wa4, lane);
            #pragma unroll
            for (int o = 16; o; o >>= 1)
                acc += __shfl_xor_sync(0xffffffffu, acc, o);
            if (lane == 0) scores[(size_t)b * S_ + s_lo + r] = acc;
            if (rn < SCHUNK) {
                #pragma unroll
                for (int i = 0; i < 4; i++) cur[i] = nxt[i];
            }
            r = rn;
        }
        __threadfence();
        __syncthreads();
        if (t == 0) atomicAdd(&g_rdy[b], 1);
    }

    // --- Phase B for both batches ---
    #pragma unroll
    for (int bi = 0; bi < BPB; bi++) {
        const int b = bs[bi];

        // wait for all 4 score chunks of batch b
        if (t == 0) {
            while (((volatile int*)g_rdy)[b] < NSPLIT) { }
        }
        __syncthreads();
        __threadfence();

        // softmax over scores[b, 0..195] (deterministic per block)
        float v0 = __ldcg(&scores[(size_t)b * S_ + t]);
        float v1 = (t + 128 < S_) ? __ldcg(&scores[(size_t)b * S_ + t + 128])
                                  : -INFINITY;
        red[t] = fmaxf(v0, v1);
        __syncthreads();
        #pragma unroll
        for (int o = 64; o; o >>= 1) {
            if (t < o) red[t] = fmaxf(red[t], red[t + o]);
            __syncthreads();
        }
        const float m = red[0];
        __syncthreads();
        float e0 = __expf(v0 - m);
        float e1 = (t + 128 < S_) ? __expf(v1 - m) : 0.f;
        es[t] = e0;
        if (t + 128 < S_) es[t + 128] = e1;
        red[t] = e0 + e1;
        __syncthreads();
        #pragma unroll
        for (int o = 64; o; o >>= 1) {
            if (t < o) red[t] += red[t + o];
            __syncthreads();
        }
        const float inv = 1.f / red[0];
        __syncthreads();
        if (t < SCHUNK) w_s[t] = es[s_lo + t] * inv;
        __syncthreads();

        // weighted partial sum over own 49 rows, 2 float4 cols per thread
        const float4* ap = (const float4*)(att + ((size_t)b * S_ + s_lo) * RNN_);
        float4 acc0 = make_float4(0.f, 0.f, 0.f, 0.f);
        float4 acc1 = make_float4(0.f, 0.f, 0.f, 0.f);

        float4 cA = __ldcs(&ap[t]);
        float4 cB = __ldcs(&ap[t + 128]);
        for (int s = 0; s < SCHUNK; s++) {
            float4 nA, nB;
            if (s + 1 < SCHUNK) {
                nA = __ldcs(&ap[(size_t)(s + 1) * (RNN_ / 4) + t]);
                nB = __ldcs(&ap[(size_t)(s + 1) * (RNN_ / 4) + t + 128]);
            }
            const float w = w_s[s];
            acc0.x += w * cA.x; acc0.y += w * cA.y;
            acc0.z += w * cA.z; acc0.w += w * cA.w;
            acc1.x += w * cB.x; acc1.y += w * cB.y;
            acc1.z += w * cB.z; acc1.w += w * cB.w;
            if (s + 1 < SCHUNK) { cA = nA; cB = nB; }
        }

        float4* op = (float4*)(part + ((size_t)split * B_ + b) * RNN_);
        op[t]       = acc0;
        op[t + 128] = acc1;

        // last block per batch: reduce 4 partials -> out, reset tickets
        __threadfence();
        __syncthreads();
        if (t == 0) {
            int ticket = atomicAdd(&g_cnt[b], 1);
            is_last = (ticket == NSPLIT - 1) ? 1 : 0;
            if (is_last) { g_cnt[b] = 0; g_rdy[b] = 0; }   // graph-replay reset
        }
        __syncthreads();

        if (is_last) {
            float4* ob = (float4*)(out + (size_t)b * RNN_);
            #pragma unroll
            for (int j = 0; j < 2; j++) {
                const int c4 = t + j * 128;
                float4 r = make_float4(0.f, 0.f, 0.f, 0.f);
                #pragma unroll
                for (int sp = 0; sp < NSPLIT; sp++) {
                    const float4 v = __ldcg(
                        (const float4*)(part + ((size_t)sp * B_ + b) * RNN_) + c4);
                    r.x += v.x; r.y += v.y; r.z += v.z; r.w += v.w;
                }
                ob[c4] = r;
            }
        }
        __syncthreads();
    }
}

// ---------------------------------------------------------------------------
extern "C" void kernel_launch(void* const* d_in, const int* in_sizes, int n_in,
                              void* d_out, int out_size)
{
    const float* h        = (const float*)d_in[0];  // [B, RNN]
    const float* att      = (const float*)d_in[1];  // [B, S, RNN]
    const float* p        = (const float*)d_in[2];  // [B, S, ATTH]
    const float* w_h2att  = (const float*)d_in[3];  // [ATTH, RNN]
    const float* b_h2att  = (const float*)d_in[4];  // [ATTH]
    const float* w_alpha  = (const float*)d_in[5];  // [1, ATTH]
    // d_in[6] = b_alpha: softmax-invariant, unused
    float* out = (float*)d_out;                     // [B, RNN]

    float *ahp_ptr = nullptr, *sc_ptr = nullptr, *part_ptr = nullptr;
    cudaGetSymbolAddress((void**)&ahp_ptr,  g_att_h_part);
    cudaGetSymbolAddress((void**)&sc_ptr,   g_scores);
    cudaGetSymbolAddress((void**)&part_ptr, g_part);

    k1_h2att<<<dim3(ATTH_ / 64, B_ / 64, KSPLIT), 128>>>(h, w_h2att, ahp_ptr);
    k23_fused<<<dim3(NSPLIT, NBY), 128>>>(p, ahp_ptr, b_h2att, w_alpha,
                                          att, sc_ptr, part_ptr, out);
}

// round 13
// speedup vs baseline: 1.0486x; 1.0486x over previous
#include <cuda_runtime.h>
#include <math.h>

// Problem constants (fixed by the dataset)
#define B_    256
#define S_    196
#define RNN_  1024
#define ATTH_ 512
#define NSPLIT 4
#define SCHUNK 49   // 196 / 4
#define KSPLIT 8    // k1 split-k factor

// Scratch (allocation-free: __device__ globals; zero-initialized)
__device__ float g_att_h_part[KSPLIT * B_ * ATTH_];  // 4 MB (k1 partials)
__device__ float g_scores[B_ * S_];                  // 200 KB
__device__ float g_part[NSPLIT * B_ * RNN_];         // 4 MB (k3 partials)
__device__ int   g_rdy[B_];                          // per-batch score tickets
__device__ int   g_cnt[B_];                          // per-batch partial tickets

// ---------------------------------------------------------------------------
// HW tanh: MUFU.TANH (abs err ~5e-4; measured output rel err ~3e-6, gate 1e-3)
// ---------------------------------------------------------------------------
__device__ __forceinline__ float tanh_approx(float x)
{
    float y;
    asm("tanh.approx.f32 %0, %1;" : "=f"(y) : "f"(x));
    return y;
}

// ---------------------------------------------------------------------------
// K1: partial att_h: part[kz][b][a] = sum_{k in chunk kz} h[b,k] * W[a,k]
// 64x64 tile, BK=32, 4x4 microtile, double-buffered smem, split-k=8.
// grid = (8, 4, 8) = 256 blocks, 256 threads.  (R10 known-good version)
// ---------------------------------------------------------------------------
__global__ __launch_bounds__(256) void k1_h2att(
    const float* __restrict__ h, const float* __restrict__ w,
    float* __restrict__ part)
{
    __shared__ float sh[2][32][68];
    __shared__ float sw[2][32][68];

    const int t  = threadIdx.x;
    const int a0 = blockIdx.x * 64;
    const int b0 = blockIdx.y * 64;
    const int kz = blockIdx.z;
    const int tx = t & 15;
    const int ty = t >> 4;
    const int lr = t >> 3;
    const int lc = (t & 7) * 4;

    const size_t kbase = (size_t)kz * (RNN_ / KSPLIT);
    const float* h0 = &h[(size_t)(b0 + lr) * RNN_ + kbase + lc];
    const float* h1 = &h[(size_t)(b0 + lr + 32) * RNN_ + kbase + lc];
    const float* w0 = &w[(size_t)(a0 + lr) * RNN_ + kbase + lc];
    const float* w1 = &w[(size_t)(a0 + lr + 32) * RNN_ + kbase + lc];

    float4 hA = *(const float4*)h0;
    float4 hB = *(const float4*)h1;
    float4 wA = *(const float4*)w0;
    float4 wB = *(const float4*)w1;
    #pragma unroll
    for (int c = 0; c < 4; c++) {
        sh[0][lc + c][lr]      = (&hA.x)[c];
        sh[0][lc + c][lr + 32] = (&hB.x)[c];
        sw[0][lc + c][lr]      = (&wA.x)[c];
        sw[0][lc + c][lr + 32] = (&wB.x)[c];
    }
    __syncthreads();

    float acc[4][4] = {};

    const int NT = RNN_ / KSPLIT / 32;   // 4 k-tiles
    #pragma unroll
    for (int kt = 0; kt < NT; kt++) {
        const int buf = kt & 1;
        if (kt + 1 < NT) {
            hA = *(const float4*)(h0 + (kt + 1) * 32);
            hB = *(const float4*)(h1 + (kt + 1) * 32);
            wA = *(const float4*)(w0 + (kt + 1) * 32);
            wB = *(const float4*)(w1 + (kt + 1) * 32);
        }
        #pragma unroll
        for (int kk = 0; kk < 32; kk++) {
            float4 hv = *(const float4*)&sh[buf][kk][ty * 4];
            float4 wv = *(const float4*)&sw[buf][kk][tx * 4];
            #pragma unroll
            for (int i = 0; i < 4; i++)
                #pragma unroll
                for (int j = 0; j < 4; j++)
                    acc[i][j] += (&hv.x)[i] * (&wv.x)[j];
        }
        __syncthreads();
        if (kt + 1 < NT) {
            const int nb = buf ^ 1;
            #pragma unroll
            for (int c = 0; c < 4; c++) {
                sh[nb][lc + c][lr]      = (&hA.x)[c];
                sh[nb][lc + c][lr + 32] = (&hB.x)[c];
                sw[nb][lc + c][lr]      = (&wA.x)[c];
                sw[nb][lc + c][lr + 32] = (&wB.x)[c];
            }
            __syncthreads();
        }
    }

    float* op = part + (size_t)kz * B_ * ATTH_;
    #pragma unroll
    for (int i = 0; i < 4; i++) {
        const int bb = b0 + ty * 4 + i;
        float4 r = make_float4(acc[i][0], acc[i][1], acc[i][2], acc[i][3]);
        *(float4*)&op[(size_t)bb * ATTH_ + a0 + tx * 4] = r;
    }
}

// ---------------------------------------------------------------------------
// helpers
// ---------------------------------------------------------------------------
__device__ __forceinline__ float row_score(
    const float4 v[4], const float4* __restrict__ ah4,
    const float4* __restrict__ wa4, int lane)
{
    float acc = 0.f;
    #pragma unroll
    for (int i = 0; i < 4; i++) {
        float4 a  = ah4[lane + i * 32];
        float4 wv = wa4[lane + i * 32];
        acc += tanh_approx(v[i].x + a.x) * wv.x + tanh_approx(v[i].y + a.y) * wv.y
             + tanh_approx(v[i].z + a.z) * wv.z + tanh_approx(v[i].w + a.w) * wv.w;
    }
    return acc;
}

__device__ __forceinline__ void load_row(
    float4 v[4], const float4* __restrict__ ps, int lane)
{
    v[0] = __ldcs(&ps[lane]);
    v[1] = __ldcs(&ps[lane + 32]);
    v[2] = __ldcs(&ps[lane + 64]);
    v[3] = __ldcs(&ps[lane + 96]);
}

// ---------------------------------------------------------------------------
// K23: fused scores + softmax + weighted sum with per-batch handoff.
// grid = (NSPLIT, B_) = (4, 256), 256 THREADS (8 warps: 2x phase-A rows in
// flight, 2x resident warps/SM vs the 128-thread version).
// Batch b's 4 blocks have contiguous IDs (x-major) -> handoff deadlock-free.
// ---------------------------------------------------------------------------
__global__ __launch_bounds__(256, 4) void k23_fused(
    const float* __restrict__ p, const float* __restrict__ att_h_part,
    const float* __restrict__ bias, const float* __restrict__ w_alpha,
    const float* __restrict__ att, float* __restrict__ scores,
    float* __restrict__ part, float* __restrict__ out)
{
    const int split = blockIdx.x;
    const int b     = blockIdx.y;
    const int t     = threadIdx.x;
    const int warp  = t >> 5, lane = t & 31;
    const int s_lo  = split * SCHUNK;

    __shared__ float4 ah4[ATTH_ / 4];
    __shared__ float4 wa4[ATTH_ / 4];
    __shared__ float  es[S_];
    __shared__ float  red[256];
    __shared__ float  w_s[SCHUNK];
    __shared__ int    is_last;

    // --- assemble att_h[b,:] from k1 partials + bias (L2-hot) ---
    if (t < ATTH_ / 4) {
        float4 r = ((const float4*)bias)[t];
        #pragma unroll
        for (int kz = 0; kz < KSPLIT; kz++) {
            const float4 v = ((const float4*)(att_h_part
                + ((size_t)kz * B_ + b) * ATTH_))[t];
            r.x += v.x; r.y += v.y; r.z += v.z; r.w += v.w;
        }
        ah4[t] = r;
        wa4[t] = ((const float4*)w_alpha)[t];
    }
    __syncthreads();

    // --- Phase A: scores for own 49 rows (8 warps, warp-per-row, pipelined) ---
    const float4* pb = (const float4*)(p + (size_t)b * S_ * ATTH_);
    {
        int r = warp;                       // warp w: rows w, w+8, ...; warp 0 hits 48
        float4 cur[4];
        if (r < SCHUNK)
            load_row(cur, pb + (size_t)(s_lo + r) * (ATTH_ / 4), lane);
        while (r < SCHUNK) {
            const int rn = r + 8;
            float4 nxt[4];
            if (rn < SCHUNK)
                load_row(nxt, pb + (size_t)(s_lo + rn) * (ATTH_ / 4), lane);
            float acc = row_score(cur, ah4, wa4, lane);
            #pragma unroll
            for (int o = 16; o; o >>= 1)
                acc += __shfl_xor_sync(0xffffffffu, acc, o);
            if (lane == 0) scores[(size_t)b * S_ + s_lo + r] = acc;
            if (rn < SCHUNK) {
                #pragma unroll
                for (int i = 0; i < 4; i++) cur[i] = nxt[i];
            }
            r = rn;
        }
    }

    // --- handoff: publish own chunk, wait for all 4 chunks of batch b ---
    __threadfence();
    __syncthreads();
    if (t == 0) {
        atomicAdd(&g_rdy[b], 1);
        while (((volatile int*)g_rdy)[b] < NSPLIT) { }
    }
    __syncthreads();
    __threadfence();

    // --- Phase B: softmax over scores[b, 0..195] (deterministic) ---
    float v0 = (t < S_) ? __ldcg(&scores[(size_t)b * S_ + t]) : -INFINITY;
    red[t] = v0;
    __syncthreads();
    #pragma unroll
    for (int o = 128; o; o >>= 1) {
        if (t < o) red[t] = fmaxf(red[t], red[t + o]);
        __syncthreads();
    }
    const float m = red[0];
    __syncthreads();
    float e0 = (t < S_) ? __expf(v0 - m) : 0.f;
    if (t < S_) es[t] = e0;
    red[t] = e0;
    __syncthreads();
    #pragma unroll
    for (int o = 128; o; o >>= 1) {
        if (t < o) red[t] += red[t + o];
        __syncthreads();
    }
    const float inv = 1.f / red[0];
    __syncthreads();
    if (t < SCHUNK) w_s[t] = es[s_lo + t] * inv;
    __syncthreads();

    // --- weighted partial sum over own 49 rows, ONE float4 col per thread,
    //     2-deep software pipeline ---
    const float4* ap = (const float4*)(att + ((size_t)b * S_ + s_lo) * RNN_);
    float4 acc0 = make_float4(0.f, 0.f, 0.f, 0.f);

    float4 c0 = __ldcs(&ap[t]);
    float4 c1 = __ldcs(&ap[(RNN_ / 4) + t]);
    for (int s = 0; s < SCHUNK; s += 2) {
        float4 n0, n1;
        if (s + 2 < SCHUNK) {
            n0 = __ldcs(&ap[(size_t)(s + 2) * (RNN_ / 4) + t]);
            if (s + 3 < SCHUNK)
                n1 = __ldcs(&ap[(size_t)(s + 3) * (RNN_ / 4) + t]);
        }
        const float w0 = w_s[s];
        acc0.x += w0 * c0.x; acc0.y += w0 * c0.y;
        acc0.z += w0 * c0.z; acc0.w += w0 * c0.w;
        if (s + 1 < SCHUNK) {
            const float w1 = w_s[s + 1];
            acc0.x += w1 * c1.x; acc0.y += w1 * c1.y;
            acc0.z += w1 * c1.z; acc0.w += w1 * c1.w;
        }
        c0 = n0; c1 = n1;
    }

    ((float4*)(part + ((size_t)split * B_ + b) * RNN_))[t] = acc0;

    // --- last block per batch: reduce 4 partials -> out, reset tickets ---
    __threadfence();
    __syncthreads();
    if (t == 0) {
        int ticket = atomicAdd(&g_cnt[b], 1);
        is_last = (ticket == NSPLIT - 1) ? 1 : 0;
        if (is_last) { g_cnt[b] = 0; g_rdy[b] = 0; }   // graph-replay reset
    }
    __syncthreads();

    if (is_last) {
        float4 r = make_float4(0.f, 0.f, 0.f, 0.f);
        #pragma unroll
        for (int sp = 0; sp < NSPLIT; sp++) {
            const float4 v = __ldcg(
                (const float4*)(part + ((size_t)sp * B_ + b) * RNN_) + t);
            r.x += v.x; r.y += v.y; r.z += v.z; r.w += v.w;
        }
        ((float4*)(out + (size_t)b * RNN_))[t] = r;
    }
}

// ---------------------------------------------------------------------------
extern "C" void kernel_launch(void* const* d_in, const int* in_sizes, int n_in,
                              void* d_out, int out_size)
{
    const float* h        = (const float*)d_in[0];  // [B, RNN]
    const float* att      = (const float*)d_in[1];  // [B, S, RNN]
    const float* p        = (const float*)d_in[2];  // [B, S, ATTH]
    const float* w_h2att  = (const float*)d_in[3];  // [ATTH, RNN]
    const float* b_h2att  = (const float*)d_in[4];  // [ATTH]
    const float* w_alpha  = (const float*)d_in[5];  // [1, ATTH]
    // d_in[6] = b_alpha: softmax-invariant, unused
    float* out = (float*)d_out;                     // [B, RNN]

    float *ahp_ptr = nullptr, *sc_ptr = nullptr, *part_ptr = nullptr;
    cudaGetSymbolAddress((void**)&ahp_ptr,  g_att_h_part);
    cudaGetSymbolAddress((void**)&sc_ptr,   g_scores);
    cudaGetSymbolAddress((void**)&part_ptr, g_part);

    k1_h2att<<<dim3(ATTH_ / 64, B_ / 64, KSPLIT), 256>>>(h, w_h2att, ahp_ptr);
    k23_fused<<<dim3(NSPLIT, B_), 256>>>(p, ahp_ptr, b_h2att, w_alpha,
                                         att, sc_ptr, part_ptr, out);
}

// round 14
// speedup vs baseline: 1.1700x; 1.1158x over previous
#include <cuda_runtime.h>
#include <math.h>

// Problem constants (fixed by the dataset)
#define B_    256
#define S_    196
#define RNN_  1024
#define ATTH_ 512
#define NSPLIT 4
#define SCHUNK 49    // 196 / 4
#define KSPLIT 8     // k1 split-k factor
#define NBG   4      // batch groups of 64 (k1 b-tiles)
#define NK1   256    // k1-role blocks (NBG groups x 8 a-tiles x 8 kz)
#define K1_PER_GROUP 64
#define NTOT  (NK1 + NSPLIT * B_)   // 1280

// Scratch (allocation-free: __device__ globals; zero-initialized)
__device__ float g_att_h_part[KSPLIT * B_ * ATTH_];  // 4 MB (k1 partials)
__device__ float g_scores[B_ * S_];                  // 200 KB
__device__ float g_part[NSPLIT * B_ * RNN_];         // 4 MB (k3 partials)
__device__ int   g_k1cnt[NBG];                       // k1 completion per bgroup
__device__ int   g_k1done[NBG];                      // consumer counts per bgroup
__device__ int   g_rdy[B_];                          // per-batch score tickets
__device__ int   g_cnt[B_];                          // per-batch partial tickets

// ---------------------------------------------------------------------------
// HW tanh: MUFU.TANH (abs err ~5e-4; measured output rel err ~3e-6, gate 1e-3)
// ---------------------------------------------------------------------------
__device__ __forceinline__ float tanh_approx(float x)
{
    float y;
    asm("tanh.approx.f32 %0, %1;" : "=f"(y) : "f"(x));
    return y;
}

__device__ __forceinline__ float row_score(
    const float4 v[4], const float4* __restrict__ ah4,
    const float4* __restrict__ wa4, int lane)
{
    float acc = 0.f;
    #pragma unroll
    for (int i = 0; i < 4; i++) {
        float4 a  = ah4[lane + i * 32];
        float4 wv = wa4[lane + i * 32];
        acc += tanh_approx(v[i].x + a.x) * wv.x + tanh_approx(v[i].y + a.y) * wv.y
             + tanh_approx(v[i].z + a.z) * wv.z + tanh_approx(v[i].w + a.w) * wv.w;
    }
    return acc;
}

__device__ __forceinline__ void load_row(
    float4 v[4], const float4* __restrict__ ps, int lane)
{
    v[0] = __ldcs(&ps[lane]);
    v[1] = __ldcs(&ps[lane + 32]);
    v[2] = __ldcs(&ps[lane + 64]);
    v[3] = __ldcs(&ps[lane + 96]);
}

// ---------------------------------------------------------------------------
// Shared-memory union: k1 role (GEMM tiles) vs k23 role (att_h + softmax)
// ---------------------------------------------------------------------------
union SmemU {
    struct {
        float sh[32][68];        // [k][b-row], 64 rows used
        float sw[32][68];        // [k][a-col]
    } k1;
    struct {
        float4 ah4[ATTH_ / 4];
        float4 wa4[ATTH_ / 4];
        float  es[S_];
        float  red[128];
        float  ws[SCHUNK];
        int    is_last;
    } a;
};

// ---------------------------------------------------------------------------
// MEGA kernel: blocks [0, NK1) run the h2att GEMM (bgroup-major so batches
// 0-63 finish first); blocks [NK1, NTOT) run the R10 fused k23 pipeline,
// gated per-bgroup on k1 completion tickets. All spins are on lower-ID
// producers or contiguous siblings -> deadlock-free under ID-ordered dispatch.
// ---------------------------------------------------------------------------
__global__ __launch_bounds__(128, 8) void mega(
    const float* __restrict__ h, const float* __restrict__ w,
    const float* __restrict__ p, const float* __restrict__ bias,
    const float* __restrict__ w_alpha, const float* __restrict__ att,
    float* __restrict__ att_h_part, float* __restrict__ scores,
    float* __restrict__ part, float* __restrict__ out)
{
    __shared__ SmemU sm;
    const int bid = blockIdx.x;
    const int t   = threadIdx.x;

    if (bid < NK1) {
        // ================= k1 role: partial GEMM =================
        // bgroup-major: group g owns blocks [64g, 64g+64)
        const int bgroup = bid >> 6;
        const int rem    = bid & 63;
        const int kz     = rem >> 3;          // 0..7
        const int a0     = (rem & 7) * 64;    // 0..448
        const int b0     = bgroup * 64;
        const int tx = t & 15;                // a-dim (x4)
        const int ty = t >> 4;                // b-dim (x8)
        const int lr = t >> 3;                // 0..15
        const int lc = (t & 7) * 4;           // 0,4,..,28

        const size_t kbase = (size_t)kz * (RNN_ / KSPLIT);   // 128-k chunk

        float4 acc[8];
        #pragma unroll
        for (int i = 0; i < 8; i++) acc[i] = make_float4(0.f, 0.f, 0.f, 0.f);

        #pragma unroll
        for (int kt = 0; kt < 4; kt++) {      // 4 tiles of BK=32
            const size_t ko = kbase + kt * 32 + lc;
            float4 v[4];
            #pragma unroll
            for (int g = 0; g < 4; g++)
                v[g] = *(const float4*)&h[(size_t)(b0 + lr + g * 16) * RNN_ + ko];
            __syncthreads();                  // prior tile's reads done
            #pragma unroll
            for (int g = 0; g < 4; g++)
                #pragma unroll
                for (int c = 0; c < 4; c++)
                    sm.k1.sh[lc + c][lr + g * 16] = (&v[g].x)[c];
            #pragma unroll
            for (int g = 0; g < 4; g++)
                v[g] = *(const float4*)&w[(size_t)(a0 + lr + g * 16) * RNN_ + ko];
            #pragma unroll
            for (int g = 0; g < 4; g++)
                #pragma unroll
                for (int c = 0; c < 4; c++)
                    sm.k1.sw[lc + c][lr + g * 16] = (&v[g].x)[c];
            __syncthreads();

            #pragma unroll
            for (int kk = 0; kk < 32; kk++) {
                float4 h0 = *(const float4*)&sm.k1.sh[kk][ty * 8];
                float4 h1 = *(const float4*)&sm.k1.sh[kk][ty * 8 + 4];
                float4 wv = *(const float4*)&sm.k1.sw[kk][tx * 4];
                #pragma unroll
                for (int j = 0; j < 4; j++) {
                    const float wj = (&wv.x)[j];
                    (&acc[0].x)[j] += h0.x * wj;
                    (&acc[1].x)[j] += h0.y * wj;
                    (&acc[2].x)[j] += h0.z * wj;
                    (&acc[3].x)[j] += h0.w * wj;
                    (&acc[4].x)[j] += h1.x * wj;
                    (&acc[5].x)[j] += h1.y * wj;
                    (&acc[6].x)[j] += h1.z * wj;
                    (&acc[7].x)[j] += h1.w * wj;
                }
            }
        }

        float* op = att_h_part + (size_t)kz * B_ * ATTH_;
        #pragma unroll
        for (int i = 0; i < 8; i++) {
            const int bb = b0 + ty * 8 + i;
            *(float4*)&op[(size_t)bb * ATTH_ + a0 + tx * 4] = acc[i];
        }

        __threadfence();                      // release partials
        __syncthreads();
        if (t == 0) atomicAdd(&g_k1cnt[bgroup], 1);
        return;
    }

    // ================= k23 role: fused scores/softmax/weighted-sum =========
    const int id    = bid - NK1;
    const int b     = id >> 2;                // batch (siblings contiguous)
    const int split = id & 3;
    const int warp  = t >> 5, lane = t & 31;
    const int s_lo  = split * SCHUNK;
    const int grp   = b >> 6;

    // --- gate on k1 completion for this batch group ---
    if (t == 0) {
        while (((volatile int*)g_k1cnt)[grp] < K1_PER_GROUP) __nanosleep(128);
    }
    __syncthreads();
    __threadfence();                          // acquire partials

    // --- assemble att_h[b,:] from k1 partials + bias ---
    {
        float4 r = ((const float4*)bias)[t];
        #pragma unroll
        for (int kz = 0; kz < KSPLIT; kz++) {
            const float4 v = ((const float4*)(att_h_part
                + ((size_t)kz * B_ + b) * ATTH_))[t];
            r.x += v.x; r.y += v.y; r.z += v.z; r.w += v.w;
        }
        sm.a.ah4[t] = r;
        sm.a.wa4[t] = ((const float4*)w_alpha)[t];
    }
    __syncthreads();

    // consumer ticket: last of the 256 consumers per group resets k1 tickets
    if (t == 0) {
        int d = atomicAdd(&g_k1done[grp], 1);
        if (d == NSPLIT * 64 - 1) { g_k1cnt[grp] = 0; g_k1done[grp] = 0; }
    }

    // --- Phase A: scores for own 49 rows (warp-per-row, pipelined) ---
    const float4* pb = (const float4*)(p + (size_t)b * S_ * ATTH_);
    {
        int r = warp;
        float4 cur[4];
        load_row(cur, pb + (size_t)(s_lo + r) * (ATTH_ / 4), lane);
        while (r < SCHUNK) {
            const int rn = r + 4;
            float4 nxt[4];
            if (rn < SCHUNK)
                load_row(nxt, pb + (size_t)(s_lo + rn) * (ATTH_ / 4), lane);
            float acc = row_score(cur, sm.a.ah4, sm.a.wa4, lane);
            #pragma unroll
            for (int o = 16; o; o >>= 1)
                acc += __shfl_xor_sync(0xffffffffu, acc, o);
            if (lane == 0) scores[(size_t)b * S_ + s_lo + r] = acc;
            if (rn < SCHUNK) {
                #pragma unroll
                for (int i = 0; i < 4; i++) cur[i] = nxt[i];
            }
            r = rn;
        }
    }

    // --- handoff: publish own chunk, wait for all 4 chunks of batch b ---
    __threadfence();
    __syncthreads();
    if (t == 0) {
        atomicAdd(&g_rdy[b], 1);
        while (((volatile int*)g_rdy)[b] < NSPLIT) __nanosleep(64);
    }
    __syncthreads();
    __threadfence();

    // --- Phase B: softmax over scores[b, 0..195] (deterministic) ---
    float v0 = __ldcg(&scores[(size_t)b * S_ + t]);
    float v1 = (t + 128 < S_) ? __ldcg(&scores[(size_t)b * S_ + t + 128])
                              : -INFINITY;
    sm.a.red[t] = fmaxf(v0, v1);
    __syncthreads();
    #pragma unroll
    for (int o = 64; o; o >>= 1) {
        if (t < o) sm.a.red[t] = fmaxf(sm.a.red[t], sm.a.red[t + o]);
        __syncthreads();
    }
    const float m = sm.a.red[0];
    __syncthreads();
    float e0 = __expf(v0 - m);
    float e1 = (t + 128 < S_) ? __expf(v1 - m) : 0.f;
    sm.a.es[t] = e0;
    if (t + 128 < S_) sm.a.es[t + 128] = e1;
    sm.a.red[t] = e0 + e1;
    __syncthreads();
    #pragma unroll
    for (int o = 64; o; o >>= 1) {
        if (t < o) sm.a.red[t] += sm.a.red[t + o];
        __syncthreads();
    }
    const float inv = 1.f / sm.a.red[0];
    __syncthreads();
    if (t < SCHUNK) sm.a.ws[t] = sm.a.es[s_lo + t] * inv;
    __syncthreads();

    // --- weighted partial sum over own 49 rows, 2 float4 cols per thread ---
    const float4* ap = (const float4*)(att + ((size_t)b * S_ + s_lo) * RNN_);
    float4 acc0 = make_float4(0.f, 0.f, 0.f, 0.f);
    float4 acc1 = make_float4(0.f, 0.f, 0.f, 0.f);

    float4 cA = __ldcs(&ap[t]);
    float4 cB = __ldcs(&ap[t + 128]);
    for (int s = 0; s < SCHUNK; s++) {
        float4 nA, nB;
        if (s + 1 < SCHUNK) {
            nA = __ldcs(&ap[(size_t)(s + 1) * (RNN_ / 4) + t]);
            nB = __ldcs(&ap[(size_t)(s + 1) * (RNN_ / 4) + t + 128]);
        }
        const float wv = sm.a.ws[s];
        acc0.x += wv * cA.x; acc0.y += wv * cA.y;
        acc0.z += wv * cA.z; acc0.w += wv * cA.w;
        acc1.x += wv * cB.x; acc1.y += wv * cB.y;
        acc1.z += wv * cB.z; acc1.w += wv * cB.w;
        if (s + 1 < SCHUNK) { cA = nA; cB = nB; }
    }

    float4* op = (float4*)(part + ((size_t)split * B_ + b) * RNN_);
    op[t]       = acc0;
    op[t + 128] = acc1;

    // --- last block per batch: reduce 4 partials -> out, reset tickets ---
    __threadfence();
    __syncthreads();
    if (t == 0) {
        int ticket = atomicAdd(&g_cnt[b], 1);
        sm.a.is_last = (ticket == NSPLIT - 1) ? 1 : 0;
        if (sm.a.is_last) { g_cnt[b] = 0; g_rdy[b] = 0; }   // replay reset
    }
    __syncthreads();

    if (sm.a.is_last) {
        #pragma unroll
        for (int j = 0; j < 2; j++) {
            const int c4 = t + j * 128;
            float4 r = make_float4(0.f, 0.f, 0.f, 0.f);
            #pragma unroll
            for (int sp = 0; sp < NSPLIT; sp++) {
                const float4 v = __ldcg(
                    (const float4*)(part + ((size_t)sp * B_ + b) * RNN_) + c4);
                r.x += v.x; r.y += v.y; r.z += v.z; r.w += v.w;
            }
            ((float4*)(out + (size_t)b * RNN_))[c4] = r;
        }
    }
}

// ---------------------------------------------------------------------------
extern "C" void kernel_launch(void* const* d_in, const int* in_sizes, int n_in,
                              void* d_out, int out_size)
{
    const float* h        = (const float*)d_in[0];  // [B, RNN]
    const float* att      = (const float*)d_in[1];  // [B, S, RNN]
    const float* p        = (const float*)d_in[2];  // [B, S, ATTH]
    const float* w_h2att  = (const float*)d_in[3];  // [ATTH, RNN]
    const float* b_h2att  = (const float*)d_in[4];  // [ATTH]
    const float* w_alpha  = (const float*)d_in[5];  // [1, ATTH]
    // d_in[6] = b_alpha: softmax-invariant, unused
    float* out = (float*)d_out;                     // [B, RNN]

    float *ahp_ptr = nullptr, *sc_ptr = nullptr, *part_ptr = nullptr;
    cudaGetSymbolAddress((void**)&ahp_ptr,  g_att_h_part);
    cudaGetSymbolAddress((void**)&sc_ptr,   g_scores);
    cudaGetSymbolAddress((void**)&part_ptr, g_part);

    mega<<<NTOT, 128>>>(h, w_h2att, p, b_h2att, w_alpha, att,
                        ahp_ptr, sc_ptr, part_ptr, out);
}